// round 8
// baseline (speedup 1.0000x reference)
#include <cuda_runtime.h>
#include <cstdint>
#include <cfloat>

#define NMAX 250000
#define EMAX 4000000
#define HID  16
#define NBIN 17
#define TPB  512

// ---- scratch (static __device__ globals) ----
__device__ int    d_degi[NMAX];
__device__ float  d_q[NMAX];
__device__ float  d_s1raw[NMAX];
__device__ __align__(16) float2 d_g[NMAX];    // {dinv, s1}
__device__ __align__(16) float2 d_nd[NMAX];   // {a=dinv*s1, dinv|j}
__device__ __align__(16) float2 d_bins[NBIN * NMAX];  // 34MB
__device__ float  d_t[HID];
__device__ unsigned d_mask[HID];              // bit j set => bin j active for k
__device__ float  d_w0fix[HID];               // wk==0 fixup selector (1 if bk>0 else 0), -1 if wk!=0
__device__ unsigned g_cnt = 0, g_phase = 0, g_cnt2 = 0;

// grid barrier: all blocks co-resident (grid sized by occupancy)
__device__ __forceinline__ void gridbar(unsigned expected) {
    __threadfence();
    __syncthreads();
    if (threadIdx.x == 0) {
        unsigned a = atomicAdd(&g_cnt, 1);
        if (a == gridDim.x - 1) {
            atomicExch(&g_cnt, 0);
            __threadfence();
            atomicAdd(&g_phase, 1);
        } else {
            while (*(volatile unsigned*)&g_phase < expected) __nanosleep(64);
        }
    }
    __syncthreads();
}

__global__ __launch_bounds__(TPB, 2)
void k_fused(const float* __restrict__ x, const int* __restrict__ ei,
             const float* __restrict__ W1, const float* __restrict__ b1,
             const float* __restrict__ W2, const float* __restrict__ b2,
             const float* __restrict__ Wfc, const float* __restrict__ bfc,
             float* __restrict__ out, int n, int E) {
    __shared__ float sW2[HID * HID], sWfc[HID * 4];
    __shared__ float sw1[HID], sb1[HID], sb2[HID], sbfc[4], st[HID], sfix[HID];
    __shared__ unsigned smask[HID];

    const int tid  = blockIdx.x * TPB + threadIdx.x;
    const int nthr = gridDim.x * TPB;
    const int* col = ei + E;

    // ── ph1: zero degi/s1raw; thread 0 computes thresholds + active masks
    for (int i = tid; i < n; i += nthr) { d_degi[i] = 0; d_s1raw[i] = 0.0f; }
    if (tid == 0) {
        float t[HID];
        for (int k = 0; k < HID; k++) {
            float w = W1[k], b = b1[k];
            t[k] = (w != 0.0f) ? (-b / w) : -FLT_MAX;
            d_t[k] = t[k];
        }
        for (int k = 0; k < HID; k++) {
            int rk = 0;
            for (int k2 = 0; k2 < HID; k2++) rk += (t[k2] < t[k]);
            float w = W1[k];
            unsigned m = 0;
            if (w > 0.0f)      { for (int j = rk + 1; j < NBIN; j++) m |= (1u << j); }
            else if (w < 0.0f) { for (int j = 0; j <= rk; j++)       m |= (1u << j); }
            d_mask[k]  = m;
            d_w0fix[k] = (w != 0.0f) ? -1.0f : ((b1[k] > 0.0f) ? 1.0f : 0.0f);
        }
    }
    gridbar(1);

    // ── ph2: degree reds + zero bins (overlapped in same phase)
    for (int e = tid; e < E; e += nthr)
        atomicAdd(d_degi + col[e], 1);
    {
        float4* b4 = reinterpret_cast<float4*>(d_bins);
        const int NB4 = NBIN * NMAX / 2;
        for (int i = tid; i < NB4; i += nthr)
            b4[i] = make_float4(0.f, 0.f, 0.f, 0.f);
    }
    gridbar(2);

    // ── ph3: node1: dinv = rsqrt(deg+1), q = dinv*x
    for (int i = tid; i < n; i += nthr) {
        float di = rsqrtf((float)(d_degi[i] + 1));
        d_q[i] = di * x[i];
        d_g[i].x = di;
    }
    gridbar(3);

    // ── ph4: edge1: s1raw[col] += q[row]
    for (int e = tid; e < E; e += nthr) {
        int r = ei[e], c = col[e];
        atomicAdd(d_s1raw + c, __ldg(d_q + r));
    }
    gridbar(4);

    // ── ph5: node2: s1, pack nd = {dinv*s1, dinv|j}
    if (threadIdx.x < HID) st[threadIdx.x] = d_t[threadIdx.x];
    __syncthreads();
    for (int i = tid; i < n; i += nthr) {
        float di = d_g[i].x;
        float s1 = di * (d_s1raw[i] + d_q[i]);
        d_g[i] = make_float2(di, s1);
        int j = 0;
#pragma unroll
        for (int k = 0; k < HID; k++) j += (st[k] < s1);
        uint32_t db = (__float_as_uint(di) & ~31u) | (uint32_t)j;
        d_nd[i] = make_float2(di * s1, __uint_as_float(db));
    }
    gridbar(5);

    // ── ph6: edge2: bins[j(row)][col] += {a, d}
    for (int e = tid; e < E; e += nthr) {
        int r = ei[e], c = col[e];
        float2 nd = __ldg(d_nd + r);
        uint32_t db = __float_as_uint(nd.y);
        int j = (int)(db & 31u);
        float dv = __uint_as_float(db & ~31u);
        float2* dst = d_bins + (size_t)j * NMAX + c;
        asm volatile("red.global.add.v2.f32 [%0], {%1, %2};"
                     :: "l"(dst), "f"(nd.x), "f"(dv) : "memory");
    }
    gridbar(6);

    // ── ph7: epilogue
    if (threadIdx.x < HID * HID) sW2[threadIdx.x] = W2[threadIdx.x];
    if (threadIdx.x < HID * 4)   sWfc[threadIdx.x] = Wfc[threadIdx.x];
    if (threadIdx.x < HID) {
        sw1[threadIdx.x] = W1[threadIdx.x]; sb1[threadIdx.x] = b1[threadIdx.x];
        sb2[threadIdx.x] = b2[threadIdx.x];
        smask[threadIdx.x] = d_mask[threadIdx.x];
        sfix[threadIdx.x]  = d_w0fix[threadIdx.x];
    }
    if (threadIdx.x < 4) sbfc[threadIdx.x] = bfc[threadIdx.x];
    __syncthreads();

    for (int i = tid; i < n; i += nthr) {
        float Ak[HID], Dk[HID];
#pragma unroll
        for (int k = 0; k < HID; k++) { Ak[k] = 0.f; Dk[k] = 0.f; }
        float TD = 0.f;
#pragma unroll
        for (int j = 0; j < NBIN; j++) {
            float2 b = __ldg(d_bins + (size_t)j * NMAX + i);
            TD += b.y;
#pragma unroll
            for (int k = 0; k < HID; k++) {
                if ((smask[k] >> j) & 1u) { Ak[k] += b.x; Dk[k] += b.y; }
            }
        }
        float2 gi = d_g[i];
        float di = gi.x, s1 = gi.y;

        float afull[HID];
#pragma unroll
        for (int k = 0; k < HID; k++) {
            float wk = sw1[k], bk = sb1[k];
            float A = Ak[k], D = Dk[k];
            float fx = sfix[k];
            if (fx >= 0.0f) { A = 0.f; D = fx * TD; }   // wk==0 case
            float agg = fmaf(wk, A, bk * D);
            float h1c = fmaxf(fmaf(s1, wk, bk), 0.f);
            afull[k] = di * fmaf(di, h1c, agg);
        }
        float h2[HID];
#pragma unroll
        for (int j = 0; j < HID; j++) {
            float acc = sb2[j];
#pragma unroll
            for (int k = 0; k < HID; k++) acc = fmaf(afull[k], sW2[k * HID + j], acc);
            h2[j] = fmaxf(acc, 0.f);
        }
#pragma unroll
        for (int j = 0; j < 4; j++) {
            float acc = sbfc[j];
#pragma unroll
            for (int k = 0; k < HID; k++) acc = fmaf(h2[k], sWfc[k * 4 + j], acc);
            out[(size_t)i * 4 + j] = acc;
        }
    }

    // ── reset barrier state for next graph replay (no wait needed)
    __syncthreads();
    if (threadIdx.x == 0) {
        unsigned a = atomicAdd(&g_cnt2, 1);
        if (a == gridDim.x - 1) {
            atomicExch(&g_phase, 0);
            atomicExch(&g_cnt2, 0);
        }
    }
}

// ---------------- launch ----------------

extern "C" void kernel_launch(void* const* d_in, const int* in_sizes, int n_in,
                              void* d_out, int out_size) {
    const float* x   = (const float*)d_in[0];
    const int*   ei  = (const int*)d_in[1];     // int32 (JAX x64 disabled)
    const float* W1  = (const float*)d_in[2];
    const float* b1  = (const float*)d_in[3];
    const float* W2  = (const float*)d_in[4];
    const float* b2  = (const float*)d_in[5];
    const float* Wfc = (const float*)d_in[6];
    const float* bfc = (const float*)d_in[7];
    float* out = (float*)d_out;

    int n = in_sizes[0];
    int E = in_sizes[1] / 2;

    // size grid so ALL blocks are co-resident (deadlock-free barrier)
    int nsm = 0, bpm = 0;
    cudaDeviceGetAttribute(&nsm, cudaDevAttrMultiProcessorCount, 0);
    cudaOccupancyMaxActiveBlocksPerMultiprocessor(&bpm, k_fused, TPB, 0);
    if (bpm < 1) bpm = 1;
    if (bpm > 2) bpm = 2;
    int grid = nsm * bpm;

    k_fused<<<grid, TPB>>>(x, ei, W1, b1, W2, b2, Wfc, bfc, out, n, E);
}

// round 9
// speedup vs baseline: 1.2487x; 1.2487x over previous
#include <cuda_runtime.h>
#include <cstdint>
#include <cfloat>

#define NMAX 250000
#define EMAX 4000000
#define HID  16
#define NBIN 17   // 16 thresholds -> 17 intervals

// ---- scratch (static __device__ globals; zero-initialized at load) ----
__device__ int    d_degi[NMAX];
__device__ float  d_s1raw[NMAX];
__device__ float  d_q[NMAX];
__device__ __align__(16) float2 d_g[NMAX];    // {dinv, s1}
__device__ __align__(16) float2 d_nd[NMAX];   // {a=dinv*s1, dinv|j in low 5 mantissa bits}
__device__ __align__(16) float2 d_bins[NBIN * NMAX];  // 34MB, self-cleaned by k_out
__device__ float  d_t[HID];
__device__ int    d_r[HID];

// ---------------- kernels ----------------

// pure degree count: deg[col]++ ; thread 0 computes thresholds + ranks
__global__ void k_deg(const int* __restrict__ ei,
                      const float* __restrict__ W1, const float* __restrict__ b1, int E) {
    int e = blockIdx.x * blockDim.x + threadIdx.x;
    if (e == 0) {
        float t[HID];
        for (int k = 0; k < HID; k++) {
            float w = W1[k], b = b1[k];
            t[k] = (w != 0.0f) ? (-b / w) : -FLT_MAX;
            d_t[k] = t[k];
        }
        for (int k = 0; k < HID; k++) {
            int r = 0;
            for (int k2 = 0; k2 < HID; k2++) r += (t[k2] < t[k]);
            d_r[k] = r;
        }
    }
    if (e < E)
        atomicAdd(d_degi + ei[E + e], 1);
}

// dinv = rsqrt(deg+1); q = dinv*x ; self-clean degi
__global__ void k_node1(const float* __restrict__ x, int n) {
    int i = blockIdx.x * blockDim.x + threadIdx.x;
    if (i < n) {
        float di = rsqrtf((float)(d_degi[i] + 1));   // +1 = self-loop
        d_degi[i] = 0;                               // clean for next replay
        d_q[i] = di * x[i];
        d_g[i].x = di;
    }
}

// s1raw[col] += q[row]
__global__ void k_edge1(const int* __restrict__ ei, int E) {
    int e = blockIdx.x * blockDim.x + threadIdx.x;
    if (e < E) {
        int r = ei[e];
        int c = ei[E + e];
        atomicAdd(d_s1raw + c, __ldg(d_q + r));
    }
}

// s1 = dinv*(s1raw + q); pack nd = {dinv*s1, dinv|j} ; self-clean s1raw
__global__ void k_node2(int n) {
    __shared__ float st[HID];
    if (threadIdx.x < HID) st[threadIdx.x] = d_t[threadIdx.x];
    __syncthreads();
    int i = blockIdx.x * blockDim.x + threadIdx.x;
    if (i < n) {
        float di = d_g[i].x;
        float s1 = di * (d_s1raw[i] + d_q[i]);
        d_s1raw[i] = 0.0f;                           // clean for next replay
        d_g[i] = make_float2(di, s1);
        int j = 0;
#pragma unroll
        for (int k = 0; k < HID; k++) j += (st[k] < s1);
        uint32_t db = (__float_as_uint(di) & ~31u) | (uint32_t)j;
        d_nd[i] = make_float2(di * s1, __uint_as_float(db));
    }
}

// layer-2 binned scatter: bins[j(row)][col] += {a_row, d_row}
__global__ void k_edge2(const int* __restrict__ ei, int E) {
    int e = blockIdx.x * blockDim.x + threadIdx.x;
    if (e < E) {
        int r = ei[e];
        int c = ei[E + e];
        float2 nd = __ldg(d_nd + r);
        uint32_t db = __float_as_uint(nd.y);
        int j = (int)(db & 31u);
        float d = __uint_as_float(db & ~31u);
        float2* dst = d_bins + (size_t)j * NMAX + c;
        asm volatile("red.global.add.v2.f32 [%0], {%1, %2};"
                     :: "l"(dst), "f"(nd.x), "f"(d) : "memory");
    }
}

// fused epilogue: reconstruct agg2 from bins (then zero them), W2+relu, Wfc -> out
__global__ void k_out(const float* __restrict__ W1, const float* __restrict__ b1,
                      const float* __restrict__ W2, const float* __restrict__ b2,
                      const float* __restrict__ Wfc, const float* __restrict__ bfc,
                      float* __restrict__ out, int n) {
    __shared__ float sW2[HID * HID], sWfc[HID * 4];
    __shared__ float sw1[HID], sb1[HID], sb2[HID], sbfc[4];
    __shared__ int   sr[HID];
    int t = threadIdx.x;
    if (t < HID * HID) sW2[t] = W2[t];
    if (t < HID * 4)   sWfc[t] = Wfc[t];
    if (t < HID) { sw1[t] = W1[t]; sb1[t] = b1[t]; sb2[t] = b2[t]; sr[t] = d_r[t]; }
    if (t < 4)   sbfc[t] = bfc[t];
    __syncthreads();

    int i = blockIdx.x * blockDim.x + t;
    if (i >= n) return;

    float aa[NBIN], dd[NBIN];
    float TD = 0.f;
#pragma unroll
    for (int j = 0; j < NBIN; j++) {
        float2* p = d_bins + (size_t)j * NMAX + i;
        float2 b = *p;
        *p = make_float2(0.f, 0.f);                  // clean for next replay
        aa[j] = b.x; dd[j] = b.y;
        TD += b.y;
    }
    float2 gi = d_g[i];
    float di = gi.x, s1 = gi.y;

    float afull[HID];
#pragma unroll
    for (int k = 0; k < HID; k++) {
        float wk = sw1[k], bk = sb1[k];
        int   rk = sr[k];
        float A = 0.f, D = 0.f;
        if (wk > 0.f) {
#pragma unroll
            for (int j = 0; j < NBIN; j++) if (j > rk) { A += aa[j]; D += dd[j]; }
        } else if (wk < 0.f) {
#pragma unroll
            for (int j = 0; j < NBIN; j++) if (j <= rk) { A += aa[j]; D += dd[j]; }
        } else {
            A = 0.f; D = (bk > 0.f) ? TD : 0.f;
        }
        float agg = fmaf(wk, A, bk * D);             // sum over real edges
        float h1c = fmaxf(fmaf(s1, wk, bk), 0.f);    // self-loop message
        afull[k] = di * fmaf(di, h1c, agg);
    }
    float h2[HID];
#pragma unroll
    for (int j = 0; j < HID; j++) {
        float acc = sb2[j];
#pragma unroll
        for (int k = 0; k < HID; k++) acc = fmaf(afull[k], sW2[k * HID + j], acc);
        h2[j] = fmaxf(acc, 0.f);
    }
#pragma unroll
    for (int j = 0; j < 4; j++) {
        float acc = sbfc[j];
#pragma unroll
        for (int k = 0; k < HID; k++) acc = fmaf(h2[k], sWfc[k * 4 + j], acc);
        out[(size_t)i * 4 + j] = acc;
    }
}

// ---------------- launch ----------------

extern "C" void kernel_launch(void* const* d_in, const int* in_sizes, int n_in,
                              void* d_out, int out_size) {
    const float* x   = (const float*)d_in[0];
    const int*   ei  = (const int*)d_in[1];     // int32 (JAX x64 disabled)
    const float* W1  = (const float*)d_in[2];
    const float* b1  = (const float*)d_in[3];
    const float* W2  = (const float*)d_in[4];
    const float* b2  = (const float*)d_in[5];
    const float* Wfc = (const float*)d_in[6];
    const float* bfc = (const float*)d_in[7];
    float* out = (float*)d_out;

    int n = in_sizes[0];
    int E = in_sizes[1] / 2;

    const int T = 256;
    int nb_nodes = (n + T - 1) / T;
    int nb_edges = (E + T - 1) / T;

    k_deg  <<<nb_edges, T>>>(ei, W1, b1, E);
    k_node1<<<nb_nodes, T>>>(x, n);
    k_edge1<<<nb_edges, T>>>(ei, E);
    k_node2<<<nb_nodes, T>>>(n);
    k_edge2<<<nb_edges, T>>>(ei, E);
    k_out  <<<nb_nodes, T>>>(W1, b1, W2, b2, Wfc, bfc, out, n);
}

// round 10
// speedup vs baseline: 1.2727x; 1.0191x over previous
#include <cuda_runtime.h>
#include <cstdint>
#include <cfloat>

#define NMAX 250000
#define EMAX 4000000
#define HID  16
#define NBIN 17   // 16 thresholds -> 17 intervals

// ---- scratch (static __device__ globals) ----
__device__ int    d_degi[NMAX];
__device__ float  d_s1raw[NMAX];
__device__ float  d_q[NMAX];
__device__ __align__(16) float2 d_g[NMAX];    // {dinv, s1}
__device__ __align__(16) float2 d_nd[NMAX];   // {a=dinv*s1, dinv|j in low 5 mantissa bits}
__device__ __align__(16) float2 d_bins[NBIN * NMAX];  // 34MB
__device__ float  d_t[HID];
__device__ int    d_r[HID];

// ---------------- kernels ----------------

// small zero: degi + s1raw; thread 0 computes thresholds + ranks
__global__ void k_zero_small(const float* __restrict__ W1, const float* __restrict__ b1, int n) {
    int i = blockIdx.x * blockDim.x + threadIdx.x;
    if (i < n) { d_degi[i] = 0; d_s1raw[i] = 0.0f; }
    if (i == 0) {
        float t[HID];
        for (int k = 0; k < HID; k++) {
            float w = W1[k], b = b1[k];
            t[k] = (w != 0.0f) ? (-b / w) : -FLT_MAX;
            d_t[k] = t[k];
        }
        for (int k = 0; k < HID; k++) {
            int r = 0;
            for (int k2 = 0; k2 < HID; k2++) r += (t[k2] < t[k]);
            d_r[k] = r;
        }
    }
}

// bins zero (runs on side stream, overlapped with deg/node1/edge1)
__global__ void k_zero_bins() {
    int tid = blockIdx.x * blockDim.x + threadIdx.x;
    int nthr = gridDim.x * blockDim.x;
    float4* b4 = reinterpret_cast<float4*>(d_bins);
    const int NB4 = NBIN * NMAX / 2;
    for (int i = tid; i < NB4; i += nthr)
        b4[i] = make_float4(0.f, 0.f, 0.f, 0.f);
}

// pure degree count: deg[col]++
__global__ void k_deg(const int* __restrict__ ei, int E) {
    int e = blockIdx.x * blockDim.x + threadIdx.x;
    if (e < E)
        atomicAdd(d_degi + ei[E + e], 1);
}

// dinv = rsqrt(deg+1); q = dinv*x
__global__ void k_node1(const float* __restrict__ x, int n) {
    int i = blockIdx.x * blockDim.x + threadIdx.x;
    if (i < n) {
        float di = rsqrtf((float)(d_degi[i] + 1));   // +1 = self-loop
        d_q[i] = di * x[i];
        d_g[i].x = di;
    }
}

// s1raw[col] += q[row]
__global__ void k_edge1(const int* __restrict__ ei, int E) {
    int e = blockIdx.x * blockDim.x + threadIdx.x;
    if (e < E) {
        int r = ei[e];
        int c = ei[E + e];
        atomicAdd(d_s1raw + c, __ldg(d_q + r));
    }
}

// s1 = dinv*(s1raw + q); pack nd = {dinv*s1, dinv|j}
__global__ void k_node2(int n) {
    __shared__ float st[HID];
    if (threadIdx.x < HID) st[threadIdx.x] = d_t[threadIdx.x];
    __syncthreads();
    int i = blockIdx.x * blockDim.x + threadIdx.x;
    if (i < n) {
        float di = d_g[i].x;
        float s1 = di * (d_s1raw[i] + d_q[i]);
        d_g[i] = make_float2(di, s1);
        int j = 0;
#pragma unroll
        for (int k = 0; k < HID; k++) j += (st[k] < s1);
        uint32_t db = (__float_as_uint(di) & ~31u) | (uint32_t)j;
        d_nd[i] = make_float2(di * s1, __uint_as_float(db));
    }
}

// layer-2 binned scatter: bins[j(row)][col] += {a_row, d_row}
__global__ void k_edge2(const int* __restrict__ ei, int E) {
    int e = blockIdx.x * blockDim.x + threadIdx.x;
    if (e < E) {
        int r = ei[e];
        int c = ei[E + e];
        float2 nd = __ldg(d_nd + r);
        uint32_t db = __float_as_uint(nd.y);
        int j = (int)(db & 31u);
        float d = __uint_as_float(db & ~31u);
        float2* dst = d_bins + (size_t)j * NMAX + c;
        asm volatile("red.global.add.v2.f32 [%0], {%1, %2};"
                     :: "l"(dst), "f"(nd.x), "f"(d) : "memory");
    }
}

// fused epilogue: reconstruct agg2 from bins, self-loop, dinv, W2+relu, Wfc -> out
__global__ void k_out(const float* __restrict__ W1, const float* __restrict__ b1,
                      const float* __restrict__ W2, const float* __restrict__ b2,
                      const float* __restrict__ Wfc, const float* __restrict__ bfc,
                      float* __restrict__ out, int n) {
    __shared__ float sW2[HID * HID], sWfc[HID * 4];
    __shared__ float sw1[HID], sb1[HID], sb2[HID], sbfc[4];
    __shared__ int   sr[HID];
    int t = threadIdx.x;
    if (t < HID * HID) sW2[t] = W2[t];
    if (t < HID * 4)   sWfc[t] = Wfc[t];
    if (t < HID) { sw1[t] = W1[t]; sb1[t] = b1[t]; sb2[t] = b2[t]; sr[t] = d_r[t]; }
    if (t < 4)   sbfc[t] = bfc[t];
    __syncthreads();

    int i = blockIdx.x * blockDim.x + t;
    if (i >= n) return;

    float aa[NBIN], dd[NBIN];
    float TD = 0.f;
#pragma unroll
    for (int j = 0; j < NBIN; j++) {
        float2 b = __ldg(d_bins + (size_t)j * NMAX + i);
        aa[j] = b.x; dd[j] = b.y;
        TD += b.y;
    }
    float2 gi = d_g[i];
    float di = gi.x, s1 = gi.y;

    float afull[HID];
#pragma unroll
    for (int k = 0; k < HID; k++) {
        float wk = sw1[k], bk = sb1[k];
        int   rk = sr[k];
        float A = 0.f, D = 0.f;
        if (wk > 0.f) {
#pragma unroll
            for (int j = 0; j < NBIN; j++) if (j > rk) { A += aa[j]; D += dd[j]; }
        } else if (wk < 0.f) {
#pragma unroll
            for (int j = 0; j < NBIN; j++) if (j <= rk) { A += aa[j]; D += dd[j]; }
        } else {
            A = 0.f; D = (bk > 0.f) ? TD : 0.f;
        }
        float agg = fmaf(wk, A, bk * D);             // sum over real edges
        float h1c = fmaxf(fmaf(s1, wk, bk), 0.f);    // self-loop message
        afull[k] = di * fmaf(di, h1c, agg);
    }
    float h2[HID];
#pragma unroll
    for (int j = 0; j < HID; j++) {
        float acc = sb2[j];
#pragma unroll
        for (int k = 0; k < HID; k++) acc = fmaf(afull[k], sW2[k * HID + j], acc);
        h2[j] = fmaxf(acc, 0.f);
    }
#pragma unroll
    for (int j = 0; j < 4; j++) {
        float acc = sbfc[j];
#pragma unroll
        for (int k = 0; k < HID; k++) acc = fmaf(h2[k], sWfc[k * 4 + j], acc);
        out[(size_t)i * 4 + j] = acc;
    }
}

// ---------------- launch ----------------

extern "C" void kernel_launch(void* const* d_in, const int* in_sizes, int n_in,
                              void* d_out, int out_size) {
    const float* x   = (const float*)d_in[0];
    const int*   ei  = (const int*)d_in[1];     // int32 (JAX x64 disabled)
    const float* W1  = (const float*)d_in[2];
    const float* b1  = (const float*)d_in[3];
    const float* W2  = (const float*)d_in[4];
    const float* b2  = (const float*)d_in[5];
    const float* Wfc = (const float*)d_in[6];
    const float* bfc = (const float*)d_in[7];
    float* out = (float*)d_out;

    int n = in_sizes[0];
    int E = in_sizes[1] / 2;

    const int T = 256;
    int nb_nodes = (n + T - 1) / T;
    int nb_edges = (E + T - 1) / T;
    const int NB4 = NBIN * NMAX / 2;
    int nb_bins  = (NB4 + T - 1) / T;

    // one-time side stream + fork/join events (resource creation only;
    // the work enqueued per call is identical every call)
    static cudaStream_t s2 = nullptr;
    static cudaEvent_t  evF = nullptr, evJ = nullptr;
    if (!s2) {
        cudaStreamCreateWithFlags(&s2, cudaStreamNonBlocking);
        cudaEventCreateWithFlags(&evF, cudaEventDisableTiming);
        cudaEventCreateWithFlags(&evJ, cudaEventDisableTiming);
    }

    // fork: bins-zero on side stream, overlapped with deg/node1/edge1
    cudaEventRecord(evF, 0);
    cudaStreamWaitEvent(s2, evF, 0);
    k_zero_bins<<<nb_bins, T, 0, s2>>>();
    cudaEventRecord(evJ, s2);

    k_zero_small<<<nb_nodes, T>>>(W1, b1, n);
    k_deg  <<<nb_edges, T>>>(ei, E);
    k_node1<<<nb_nodes, T>>>(x, n);
    k_edge1<<<nb_edges, T>>>(ei, E);
    k_node2<<<nb_nodes, T>>>(n);

    // join: bins must be zeroed before edge2 scatters into them
    cudaStreamWaitEvent(0, evJ, 0);
    k_edge2<<<nb_edges, T>>>(ei, E);
    k_out  <<<nb_nodes, T>>>(W1, b1, W2, b2, Wfc, bfc, out, n);
}

// round 11
// speedup vs baseline: 1.3319x; 1.0466x over previous
#include <cuda_runtime.h>
#include <cstdint>
#include <cfloat>

#define NMAX 250000
#define EMAX 4000000
#define HID  16
#define NBIN 17   // 16 thresholds -> 17 intervals

// ---- scratch (static __device__ globals) ----
__device__ int    d_degi[NMAX];
__device__ float  d_s1raw[NMAX];
__device__ float  d_q[NMAX];
__device__ float  d_dinv[NMAX];
__device__ __align__(16) float2 d_nd[NMAX];   // {a=dinv*s1, dinv|j in low 5 mantissa bits}
__device__ __align__(16) float2 d_bins[NBIN * NMAX];  // 34MB
__device__ float  d_t[HID];
__device__ int    d_r[HID];

// ---------------- kernels ----------------

// zero bins + degi + s1raw; thread 0 computes thresholds + ranks (R7 structure)
__global__ void k_zero(const float* __restrict__ W1, const float* __restrict__ b1, int n) {
    int tid = blockIdx.x * blockDim.x + threadIdx.x;
    int nthr = gridDim.x * blockDim.x;

    float4* b4 = reinterpret_cast<float4*>(d_bins);
    const int NB4 = NBIN * NMAX / 2;
    for (int i = tid; i < NB4; i += nthr)
        b4[i] = make_float4(0.f, 0.f, 0.f, 0.f);
    if (tid < n) { d_degi[tid] = 0; d_s1raw[tid] = 0.0f; }

    if (tid == 0) {
        float t[HID];
        for (int k = 0; k < HID; k++) {
            float w = W1[k], b = b1[k];
            t[k] = (w != 0.0f) ? (-b / w) : -FLT_MAX;
            d_t[k] = t[k];
        }
        for (int k = 0; k < HID; k++) {
            int r = 0;
            for (int k2 = 0; k2 < HID; k2++) r += (t[k2] < t[k]);
            d_r[k] = r;
        }
    }
}

// pure degree count: deg[col]++
__global__ void k_deg(const int* __restrict__ ei, int E) {
    int e = blockIdx.x * blockDim.x + threadIdx.x;
    if (e < E)
        atomicAdd(d_degi + ei[E + e], 1);
}

// dinv = rsqrt(deg+1); q = dinv*x   (2 nodes/thread, vectorized)
__global__ void k_node1(const float* __restrict__ x, int n) {
    int i2 = blockIdx.x * blockDim.x + threadIdx.x;
    int i = i2 * 2;
    if (i + 1 < n) {
        int2   dg = *reinterpret_cast<const int2*>(d_degi + i);
        float2 xv = *reinterpret_cast<const float2*>(x + i);
        float2 dv, qv;
        dv.x = rsqrtf((float)(dg.x + 1));
        dv.y = rsqrtf((float)(dg.y + 1));
        qv.x = dv.x * xv.x;
        qv.y = dv.y * xv.y;
        *reinterpret_cast<float2*>(d_dinv + i) = dv;
        *reinterpret_cast<float2*>(d_q + i) = qv;
    } else if (i < n) {
        float di = rsqrtf((float)(d_degi[i] + 1));
        d_dinv[i] = di;
        d_q[i] = di * x[i];
    }
}

// s1raw[col] += q[row]
__global__ void k_edge1(const int* __restrict__ ei, int E) {
    int e = blockIdx.x * blockDim.x + threadIdx.x;
    if (e < E) {
        int r = ei[e];
        int c = ei[E + e];
        atomicAdd(d_s1raw + c, __ldg(d_q + r));
    }
}

// s1 = dinv*(s1raw + q); pack nd = {dinv*s1, dinv|j}   (2 nodes/thread)
__global__ void k_node2(int n) {
    __shared__ float st[HID];
    if (threadIdx.x < HID) st[threadIdx.x] = d_t[threadIdx.x];
    __syncthreads();
    int i2 = blockIdx.x * blockDim.x + threadIdx.x;
    int i = i2 * 2;
    if (i + 1 < n) {
        float2 dv = *reinterpret_cast<const float2*>(d_dinv + i);
        float2 sv = *reinterpret_cast<const float2*>(d_s1raw + i);
        float2 qv = *reinterpret_cast<const float2*>(d_q + i);
        float s1a = dv.x * (sv.x + qv.x);
        float s1b = dv.y * (sv.y + qv.y);
        int ja = 0, jb = 0;
#pragma unroll
        for (int k = 0; k < HID; k++) { ja += (st[k] < s1a); jb += (st[k] < s1b); }
        float4 o;
        o.x = dv.x * s1a;
        o.y = __uint_as_float((__float_as_uint(dv.x) & ~31u) | (uint32_t)ja);
        o.z = dv.y * s1b;
        o.w = __uint_as_float((__float_as_uint(dv.y) & ~31u) | (uint32_t)jb);
        *reinterpret_cast<float4*>(d_nd + i) = o;
    } else if (i < n) {
        float di = d_dinv[i];
        float s1 = di * (d_s1raw[i] + d_q[i]);
        int j = 0;
#pragma unroll
        for (int k = 0; k < HID; k++) j += (st[k] < s1);
        uint32_t db = (__float_as_uint(di) & ~31u) | (uint32_t)j;
        d_nd[i] = make_float2(di * s1, __uint_as_float(db));
    }
}

// layer-2 binned scatter: bins[j(row)][col] += {a_row, d_row}
__global__ void k_edge2(const int* __restrict__ ei, int E) {
    int e = blockIdx.x * blockDim.x + threadIdx.x;
    if (e < E) {
        int r = ei[e];
        int c = ei[E + e];
        float2 nd = __ldg(d_nd + r);
        uint32_t db = __float_as_uint(nd.y);
        int j = (int)(db & 31u);
        float d = __uint_as_float(db & ~31u);
        float2* dst = d_bins + (size_t)j * NMAX + c;
        asm volatile("red.global.add.v2.f32 [%0], {%1, %2};"
                     :: "l"(dst), "f"(nd.x), "f"(d) : "memory");
    }
}

// fused epilogue: reconstruct agg2 from bins, self-loop, dinv, W2+relu, Wfc -> out
__global__ void k_out(const float* __restrict__ W1, const float* __restrict__ b1,
                      const float* __restrict__ W2, const float* __restrict__ b2,
                      const float* __restrict__ Wfc, const float* __restrict__ bfc,
                      float* __restrict__ out, int n) {
    __shared__ float sW2[HID * HID], sWfc[HID * 4];
    __shared__ float sw1[HID], sb1[HID], sb2[HID], sbfc[4];
    __shared__ int   sr[HID];
    int t = threadIdx.x;
    if (t < HID * HID) sW2[t] = W2[t];
    if (t < HID * 4)   sWfc[t] = Wfc[t];
    if (t < HID) { sw1[t] = W1[t]; sb1[t] = b1[t]; sb2[t] = b2[t]; sr[t] = d_r[t]; }
    if (t < 4)   sbfc[t] = bfc[t];
    __syncthreads();

    int i = blockIdx.x * blockDim.x + t;
    if (i >= n) return;

    float aa[NBIN], dd[NBIN];
    float TD = 0.f;
#pragma unroll
    for (int j = 0; j < NBIN; j++) {
        float2 b = __ldg(d_bins + (size_t)j * NMAX + i);
        aa[j] = b.x; dd[j] = b.y;
        TD += b.y;
    }
    // reconstruct {dinv, s1} from nd
    float2 nd = d_nd[i];
    float di = __uint_as_float(__float_as_uint(nd.y) & ~31u);
    float s1 = __fdividef(nd.x, di);

    float afull[HID];
#pragma unroll
    for (int k = 0; k < HID; k++) {
        float wk = sw1[k], bk = sb1[k];
        int   rk = sr[k];
        float A = 0.f, D = 0.f;
        if (wk > 0.f) {
#pragma unroll
            for (int j = 0; j < NBIN; j++) if (j > rk) { A += aa[j]; D += dd[j]; }
        } else if (wk < 0.f) {
#pragma unroll
            for (int j = 0; j < NBIN; j++) if (j <= rk) { A += aa[j]; D += dd[j]; }
        } else {
            A = 0.f; D = (bk > 0.f) ? TD : 0.f;
        }
        float agg = fmaf(wk, A, bk * D);             // sum over real edges
        float h1c = fmaxf(fmaf(s1, wk, bk), 0.f);    // self-loop message
        afull[k] = di * fmaf(di, h1c, agg);
    }
    float h2[HID];
#pragma unroll
    for (int j = 0; j < HID; j++) {
        float acc = sb2[j];
#pragma unroll
        for (int k = 0; k < HID; k++) acc = fmaf(afull[k], sW2[k * HID + j], acc);
        h2[j] = fmaxf(acc, 0.f);
    }
#pragma unroll
    for (int j = 0; j < 4; j++) {
        float acc = sbfc[j];
#pragma unroll
        for (int k = 0; k < HID; k++) acc = fmaf(h2[k], sWfc[k * 4 + j], acc);
        out[(size_t)i * 4 + j] = acc;
    }
}

// ---------------- launch ----------------

extern "C" void kernel_launch(void* const* d_in, const int* in_sizes, int n_in,
                              void* d_out, int out_size) {
    const float* x   = (const float*)d_in[0];
    const int*   ei  = (const int*)d_in[1];     // int32 (JAX x64 disabled)
    const float* W1  = (const float*)d_in[2];
    const float* b1  = (const float*)d_in[3];
    const float* W2  = (const float*)d_in[4];
    const float* b2  = (const float*)d_in[5];
    const float* Wfc = (const float*)d_in[6];
    const float* bfc = (const float*)d_in[7];
    float* out = (float*)d_out;

    int n = in_sizes[0];
    int E = in_sizes[1] / 2;

    const int T = 256;
    int nb_nodes  = (n + T - 1) / T;
    int nb_nodes2 = ((n + 1) / 2 + T - 1) / T;
    int nb_edges  = (E + T - 1) / T;
    const int NB4 = NBIN * NMAX / 2;
    int nb_zero   = (NB4 + T - 1) / T;          // covers bins; tid<n covers deg/s1raw

    k_zero <<<nb_zero,   T>>>(W1, b1, n);
    k_deg  <<<nb_edges,  T>>>(ei, E);
    k_node1<<<nb_nodes2, T>>>(x, n);
    k_edge1<<<nb_edges,  T>>>(ei, E);
    k_node2<<<nb_nodes2, T>>>(n);
    k_edge2<<<nb_edges,  T>>>(ei, E);
    k_out  <<<nb_nodes,  T>>>(W1, b1, W2, b2, Wfc, bfc, out, n);
}

// round 12
// speedup vs baseline: 1.4040x; 1.0542x over previous
#include <cuda_runtime.h>
#include <cstdint>
#include <cfloat>

#define NMAX 250000
#define EMAX 4000000
#define HID  16
#define NBIN 17   // 16 thresholds -> 17 intervals
#define TOUT 256

// ---- scratch (static __device__ globals) ----
__device__ int    d_degi[NMAX];
__device__ float  d_s1raw[NMAX];
__device__ float  d_q[NMAX];
__device__ float  d_dinv[NMAX];
__device__ __align__(16) float2 d_nd[NMAX];   // {a=dinv*s1, dinv|j in low 5 mantissa bits}
__device__ __align__(16) float2 d_bins[NBIN * NMAX];  // 34MB
__device__ float  d_t[HID];
__device__ int    d_r[HID];
// branchless epilogue coefficients: A = c0*TA + c1*PA[rk], D = d0*TD + d1*PD[rk]
__device__ float  d_c0[HID], d_c1[HID], d_d0[HID], d_d1[HID];

// ---------------- kernels ----------------

// zero bins + degi + s1raw; thread 0 computes thresholds + ranks + coeffs
__global__ void k_zero(const float* __restrict__ W1, const float* __restrict__ b1, int n) {
    int tid = blockIdx.x * blockDim.x + threadIdx.x;
    int nthr = gridDim.x * blockDim.x;

    float4* b4 = reinterpret_cast<float4*>(d_bins);
    const int NB4 = NBIN * NMAX / 2;
    for (int i = tid; i < NB4; i += nthr)
        b4[i] = make_float4(0.f, 0.f, 0.f, 0.f);
    if (tid < n) { d_degi[tid] = 0; d_s1raw[tid] = 0.0f; }

    if (tid == 0) {
        float t[HID];
        for (int k = 0; k < HID; k++) {
            float w = W1[k], b = b1[k];
            t[k] = (w != 0.0f) ? (-b / w) : -FLT_MAX;
            d_t[k] = t[k];
        }
        for (int k = 0; k < HID; k++) {
            int r = 0;
            for (int k2 = 0; k2 < HID; k2++) r += (t[k2] < t[k]);
            d_r[k] = r;
            float w = W1[k];
            if (w > 0.0f)      { d_c0[k] = 1.f; d_c1[k] = -1.f; d_d0[k] = 1.f; d_d1[k] = -1.f; }
            else if (w < 0.0f) { d_c0[k] = 0.f; d_c1[k] =  1.f; d_d0[k] = 0.f; d_d1[k] =  1.f; }
            else               { d_c0[k] = 0.f; d_c1[k] =  0.f;
                                 d_d0[k] = (b1[k] > 0.0f) ? 1.f : 0.f; d_d1[k] = 0.f; }
        }
    }
}

// pure degree count: deg[col]++
__global__ void k_deg(const int* __restrict__ ei, int E) {
    int e = blockIdx.x * blockDim.x + threadIdx.x;
    if (e < E)
        atomicAdd(d_degi + ei[E + e], 1);
}

// dinv = rsqrt(deg+1); q = dinv*x   (2 nodes/thread)
__global__ void k_node1(const float* __restrict__ x, int n) {
    int i = (blockIdx.x * blockDim.x + threadIdx.x) * 2;
    if (i + 1 < n) {
        int2   dg = *reinterpret_cast<const int2*>(d_degi + i);
        float2 xv = *reinterpret_cast<const float2*>(x + i);
        float2 dv, qv;
        dv.x = rsqrtf((float)(dg.x + 1));
        dv.y = rsqrtf((float)(dg.y + 1));
        qv.x = dv.x * xv.x;
        qv.y = dv.y * xv.y;
        *reinterpret_cast<float2*>(d_dinv + i) = dv;
        *reinterpret_cast<float2*>(d_q + i) = qv;
    } else if (i < n) {
        float di = rsqrtf((float)(d_degi[i] + 1));
        d_dinv[i] = di;
        d_q[i] = di * x[i];
    }
}

// s1raw[col] += q[row]
__global__ void k_edge1(const int* __restrict__ ei, int E) {
    int e = blockIdx.x * blockDim.x + threadIdx.x;
    if (e < E) {
        int r = ei[e];
        int c = ei[E + e];
        atomicAdd(d_s1raw + c, __ldg(d_q + r));
    }
}

// s1 = dinv*(s1raw + q); pack nd = {dinv*s1, dinv|j}   (2 nodes/thread)
__global__ void k_node2(int n) {
    __shared__ float st[HID];
    if (threadIdx.x < HID) st[threadIdx.x] = d_t[threadIdx.x];
    __syncthreads();
    int i = (blockIdx.x * blockDim.x + threadIdx.x) * 2;
    if (i + 1 < n) {
        float2 dv = *reinterpret_cast<const float2*>(d_dinv + i);
        float2 sv = *reinterpret_cast<const float2*>(d_s1raw + i);
        float2 qv = *reinterpret_cast<const float2*>(d_q + i);
        float s1a = dv.x * (sv.x + qv.x);
        float s1b = dv.y * (sv.y + qv.y);
        int ja = 0, jb = 0;
#pragma unroll
        for (int k = 0; k < HID; k++) { ja += (st[k] < s1a); jb += (st[k] < s1b); }
        float4 o;
        o.x = dv.x * s1a;
        o.y = __uint_as_float((__float_as_uint(dv.x) & ~31u) | (uint32_t)ja);
        o.z = dv.y * s1b;
        o.w = __uint_as_float((__float_as_uint(dv.y) & ~31u) | (uint32_t)jb);
        *reinterpret_cast<float4*>(d_nd + i) = o;
    } else if (i < n) {
        float di = d_dinv[i];
        float s1 = di * (d_s1raw[i] + d_q[i]);
        int j = 0;
#pragma unroll
        for (int k = 0; k < HID; k++) j += (st[k] < s1);
        uint32_t db = (__float_as_uint(di) & ~31u) | (uint32_t)j;
        d_nd[i] = make_float2(di * s1, __uint_as_float(db));
    }
}

// layer-2 binned scatter: bins[j(row)][col] += {a_row, d_row}
__global__ void k_edge2(const int* __restrict__ ei, int E) {
    int e = blockIdx.x * blockDim.x + threadIdx.x;
    if (e < E) {
        int r = ei[e];
        int c = ei[E + e];
        float2 nd = __ldg(d_nd + r);
        uint32_t db = __float_as_uint(nd.y);
        int j = (int)(db & 31u);
        float d = __uint_as_float(db & ~31u);
        float2* dst = d_bins + (size_t)j * NMAX + c;
        asm volatile("red.global.add.v2.f32 [%0], {%1, %2};"
                     :: "l"(dst), "f"(nd.x), "f"(d) : "memory");
    }
}

// fused epilogue: prefix-sum bins, smem dynamic-index select, W2+relu, Wfc -> out
__global__ void k_out(const float* __restrict__ W1, const float* __restrict__ b1,
                      const float* __restrict__ W2, const float* __restrict__ b2,
                      const float* __restrict__ Wfc, const float* __restrict__ bfc,
                      float* __restrict__ out, int n) {
    __shared__ float sPA[NBIN * TOUT];   // [j][tid]
    __shared__ float sPD[NBIN * TOUT];
    __shared__ float sW2[HID * HID], sWfc[HID * 4];
    __shared__ float sw1[HID], sb1[HID], sb2[HID], sbfc[4];
    __shared__ float sc0[HID], sc1[HID], sd0[HID], sd1[HID];
    __shared__ int   sr[HID];
    int t = threadIdx.x;
    if (t < HID * HID) sW2[t] = W2[t];
    if (t < HID * 4)   sWfc[t] = Wfc[t];
    if (t < HID) {
        sw1[t] = W1[t]; sb1[t] = b1[t]; sb2[t] = b2[t]; sr[t] = d_r[t];
        sc0[t] = d_c0[t]; sc1[t] = d_c1[t]; sd0[t] = d_d0[t]; sd1[t] = d_d1[t];
    }
    if (t < 4)   sbfc[t] = bfc[t];
    __syncthreads();

    int i = blockIdx.x * TOUT + t;
    if (i >= n) return;

    // running prefix over bins -> smem for dynamic-rank select
    float pa = 0.f, pd = 0.f;
#pragma unroll
    for (int j = 0; j < NBIN; j++) {
        float2 b = __ldg(d_bins + (size_t)j * NMAX + i);
        pa += b.x; pd += b.y;
        sPA[j * TOUT + t] = pa;
        sPD[j * TOUT + t] = pd;
    }
    float TA = pa, TD = pd;

    // reconstruct {dinv, s1} from nd
    float2 nd = d_nd[i];
    float di = __uint_as_float(__float_as_uint(nd.y) & ~31u);
    float s1 = __fdividef(nd.x, di);

    float afull[HID];
#pragma unroll
    for (int k = 0; k < HID; k++) {
        float wk = sw1[k], bk = sb1[k];
        int   rk = sr[k];
        float PAr = sPA[rk * TOUT + t];
        float PDr = sPD[rk * TOUT + t];
        float A = fmaf(sc0[k], TA, sc1[k] * PAr);
        float D = fmaf(sd0[k], TD, sd1[k] * PDr);
        float agg = fmaf(wk, A, bk * D);             // sum over real edges
        float h1c = fmaxf(fmaf(s1, wk, bk), 0.f);    // self-loop message
        afull[k] = di * fmaf(di, h1c, agg);
    }
    float h2[HID];
#pragma unroll
    for (int j = 0; j < HID; j++) {
        float acc = sb2[j];
#pragma unroll
        for (int k = 0; k < HID; k++) acc = fmaf(afull[k], sW2[k * HID + j], acc);
        h2[j] = fmaxf(acc, 0.f);
    }
#pragma unroll
    for (int j = 0; j < 4; j++) {
        float acc = sbfc[j];
#pragma unroll
        for (int k = 0; k < HID; k++) acc = fmaf(h2[k], sWfc[k * 4 + j], acc);
        out[(size_t)i * 4 + j] = acc;
    }
}

// ---------------- launch ----------------

extern "C" void kernel_launch(void* const* d_in, const int* in_sizes, int n_in,
                              void* d_out, int out_size) {
    const float* x   = (const float*)d_in[0];
    const int*   ei  = (const int*)d_in[1];     // int32 (JAX x64 disabled)
    const float* W1  = (const float*)d_in[2];
    const float* b1  = (const float*)d_in[3];
    const float* W2  = (const float*)d_in[4];
    const float* b2  = (const float*)d_in[5];
    const float* Wfc = (const float*)d_in[6];
    const float* bfc = (const float*)d_in[7];
    float* out = (float*)d_out;

    int n = in_sizes[0];
    int E = in_sizes[1] / 2;

    const int T = 256;
    int nb_nodes  = (n + TOUT - 1) / TOUT;
    int nb_nodes2 = ((n + 1) / 2 + T - 1) / T;
    int nb_edges  = (E + T - 1) / T;
    const int NB4 = NBIN * NMAX / 2;
    int nb_zero   = (NB4 + T - 1) / T;          // covers bins; tid<n covers deg/s1raw

    k_zero <<<nb_zero,   T>>>(W1, b1, n);
    k_deg  <<<nb_edges,  T>>>(ei, E);
    k_node1<<<nb_nodes2, T>>>(x, n);
    k_edge1<<<nb_edges,  T>>>(ei, E);
    k_node2<<<nb_nodes2, T>>>(n);
    k_edge2<<<nb_edges,  T>>>(ei, E);
    k_out  <<<nb_nodes,  TOUT>>>(W1, b1, W2, b2, Wfc, bfc, out, n);
}